// round 12
// baseline (speedup 1.0000x reference)
#include <cuda_runtime.h>
#include <cuda_fp16.h>

#define Wd 192
#define Hd 192
#define HW (192*192)
#define BATCH 4
#define PIX (BATCH*HW)
#define INC 256

// ---------------- scratch (no allocations allowed) ----------------
__device__ __align__(16) float g_h0[BATCH*16*HW];
__device__ __align__(16) float g_h1[BATCH*16*HW];
__device__ __align__(16) float g_cat[(size_t)BATCH*288*HW];
__device__ __align__(16) float g_wt[288*128];

__constant__ int c_dy8[9] = {-1,-1,-1, 0, 1, 1, 1, 0, 0};
__constant__ int c_dx8[9] = {-1, 0, 1, 1, 1, 0,-1,-1, 0};

// ---------------- helpers ----------------
typedef unsigned long long ull;
union F2U { float2 f; ull u; };

__device__ __forceinline__ ull fma2(ull a, ull b, ull c) {
    ull d;
    asm("fma.rn.f32x2 %0, %1, %2, %3;" : "=l"(d) : "l"(a), "l"(b), "l"(c));
    return d;
}
__device__ __forceinline__ ull pack2(float x, float y) {
    F2U t; t.f = make_float2(x, y); return t.u;
}
__device__ __forceinline__ unsigned h2u(__half2 h) { return *(unsigned*)&h; }
__device__ __forceinline__ __half2 u2h(unsigned u) { return *(__half2*)&u; }

__device__ __forceinline__ void cp16(unsigned dst, const void* src) {
    asm volatile("cp.async.cg.shared.global [%0], [%1], 16;" :: "r"(dst), "l"(src));
}

// ================= K0: transpose out_w (128,288) -> (288,128) =================
__global__ void wt_kernel(const float* __restrict__ out_w) {
    int idx = blockIdx.x * 256 + threadIdx.x;
    if (idx < 128 * 288) {
        int o = idx / 288, i = idx % 288;
        g_wt[i * 128 + o] = out_w[idx];
    }
}

// ================= K1: fused 1x1 + 3x3 projection (2 px/thread) =================
__global__ void __launch_bounds__(128) proj_kernel(
    const float* __restrict__ cen,
    const float* __restrict__ w0, const float* __restrict__ b0,
    const float* __restrict__ w1, const float* __restrict__ b1)
{
    __shared__ __align__(16) float s_cen[16][18][18];
    __shared__ __align__(16) float s_w1[16][9][16];
    __shared__ __align__(16) float s_w0[16][16];

    const int tx = threadIdx.x;
    const int ty = threadIdx.y;
    const int tid = ty * 16 + tx;
    const int x0 = blockIdx.x * 16, y0 = blockIdx.y * 16;
    const int b  = blockIdx.z;

    ull acc0[2][8], acc1[2][8];
#pragma unroll
    for (int p = 0; p < 2; p++)
#pragma unroll
        for (int o = 0; o < 8; o++) { acc0[p][o] = 0ull; acc1[p][o] = 0ull; }

#pragma unroll 1
    for (int cc = 0; cc < 16; cc++) {
        for (int idx = tid; idx < 16 * 324; idx += 128) {
            int ci = idx / 324, rem = idx % 324;
            int ly = rem / 18, lx = rem % 18;
            int gy = y0 - 1 + ly, gx = x0 - 1 + lx;
            float v = 0.f;
            if ((unsigned)gy < (unsigned)Hd && (unsigned)gx < (unsigned)Wd)
                v = cen[(size_t)(b * INC + cc * 16 + ci) * HW + gy * Wd + gx];
            s_cen[ci][ly][lx] = v;
        }
        for (int idx = tid; idx < 2304; idx += 128) {
            int ci = idx / 144, rem = idx % 144;
            int t = rem / 16, o = rem % 16;
            s_w1[ci][t][o] = w1[(o * INC + cc * 16 + ci) * 9 + t];
        }
        for (int ii = tid; ii < 256; ii += 128) {
            int ci = ii / 16, o = ii % 16;
            s_w0[ci][o] = w0[o * INC + cc * 16 + ci];
        }
        __syncthreads();

#pragma unroll 1
        for (int ci = 0; ci < 16; ci++) {
#pragma unroll
            for (int px = 0; px < 2; px++) {
                const int ly = ty + px * 8;
                float v[9];
#pragma unroll
                for (int r = 0; r < 3; r++)
#pragma unroll
                    for (int c = 0; c < 3; c++)
                        v[r * 3 + c] = s_cen[ci][ly + r][tx + c];

                ull cv = pack2(v[4], v[4]);
                const ull* w0p = reinterpret_cast<const ull*>(&s_w0[ci][0]);
#pragma unroll
                for (int o2 = 0; o2 < 8; o2++)
                    acc0[px][o2] = fma2(cv, w0p[o2], acc0[px][o2]);
#pragma unroll
                for (int t = 0; t < 9; t++) {
                    ull tv = pack2(v[t], v[t]);
                    const ull* wp = reinterpret_cast<const ull*>(&s_w1[ci][t][0]);
#pragma unroll
                    for (int o2 = 0; o2 < 8; o2++)
                        acc1[px][o2] = fma2(tv, wp[o2], acc1[px][o2]);
                }
            }
        }
        __syncthreads();
    }

#pragma unroll
    for (int px = 0; px < 2; px++) {
        const int y = y0 + ty + px * 8, x = x0 + tx;
        const size_t base = (size_t)b * 16 * HW + (size_t)y * Wd + x;
#pragma unroll
        for (int o2 = 0; o2 < 8; o2++) {
            F2U a; a.u = acc0[px][o2];
            g_h0[base + (size_t)(2 * o2) * HW]     = a.f.x + b0[2 * o2];
            g_h0[base + (size_t)(2 * o2 + 1) * HW] = a.f.y + b0[2 * o2 + 1];
            F2U c; c.u = acc1[px][o2];
            g_h1[base + (size_t)(2 * o2) * HW]     = c.f.x + b1[2 * o2];
            g_h1[base + (size_t)(2 * o2 + 1) * HW] = c.f.y + b1[2 * o2 + 1];
        }
    }
}

// ================= K2: attention v4 — 256 thr, 1 px/thread, fp16 smem ===========
#define NT4 256
#define SO1_OFF 6912                        // floats; sO1 = uint2[9*4*NT4]
#define SO3_OFF (6912 + 9*4*2*NT4)          // +18432 floats
#define SMTOT4  ((6912 + 2*9*4*2*NT4) * 4)  // 175104 B

__global__ void __launch_bounds__(NT4) attn_kernel(
    const float* __restrict__ w1_0, const float* __restrict__ w2_0, const float* __restrict__ w3_0,
    const float* __restrict__ w1_1, const float* __restrict__ w2_1, const float* __restrict__ w3_1,
    const float* __restrict__ scale)
{
    extern __shared__ float sm[];
    float* s_w = sm;                              // w1t | w2t | w3t [(g*16+c)*16+d]
    uint2* sO1 = (uint2*)(sm + SO1_OFF);          // [(q*4+dpp)*NT4 + tid]
    uint2* sO3 = (uint2*)(sm + SO3_OFF);

    const int tid = threadIdx.x;
    const int pid = blockIdx.x * NT4 + tid;
    const int b  = pid / HW;
    const int hw = pid % HW;
    const int y = hw / Wd, x = hw % Wd;

#pragma unroll 1
    for (int br = 0; br < 2; br++) {
        const float* h  = (br ? g_h1 : g_h0) + (size_t)b * 16 * HW;
        const float* w1 = br ? w1_1 : w1_0;
        const float* w2 = br ? w2_1 : w2_0;
        const float* w3 = br ? w3_1 : w3_0;
        const int   s  = br ? 5 : 1;
        const float sc = scale[br];

        __syncthreads();
        for (int i = tid; i < 2304; i += NT4) {
            int g = i >> 8; int rem = i & 255;
            int d = rem >> 4, c = rem & 15;
            int tix = ((g * 16 + c) << 4) + d;
            s_w[tix]        = w1[i];
            s_w[2304 + tix] = w2[i];
            s_w[4608 + tix] = w3[i];
        }
        __syncthreads();

        // ---------- phase 1: o1[q], o3[q] -> fp16 smem (tid-private slots) ------
#pragma unroll 1
        for (int q = 0; q < 9; q++) {
            const int yy = y + c_dy8[q] * s;
            const int xx = x + c_dx8[q] * s;
            const bool ok = ((unsigned)yy < (unsigned)Hd) && ((unsigned)xx < (unsigned)Wd);
            const float sgn = (q == 8) ? 1.f : -1.f;
            const float* hp = h + yy * Wd + xx;

            float xv[16];
#pragma unroll
            for (int c = 0; c < 16; c++)
                xv[c] = ok ? sgn * hp[c * HW] : 0.f;

            ull a1[8], a3[8];
#pragma unroll
            for (int dp = 0; dp < 8; dp++) { a1[dp] = 0ull; a3[dp] = 0ull; }
#pragma unroll
            for (int c = 0; c < 16; c++) {
                ull xc = pack2(xv[c], xv[c]);
                const ulonglong2* wp1 = (const ulonglong2*)(s_w + (((q * 16 + c) << 4)));
                const ulonglong2* wp3 = (const ulonglong2*)(s_w + 4608 + (((q * 16 + c) << 4)));
#pragma unroll
                for (int j = 0; j < 4; j++) {
                    ulonglong2 wv1 = wp1[j];
                    a1[2*j]   = fma2(xc, wv1.x, a1[2*j]);
                    a1[2*j+1] = fma2(xc, wv1.y, a1[2*j+1]);
                    ulonglong2 wv3 = wp3[j];
                    a3[2*j]   = fma2(xc, wv3.x, a3[2*j]);
                    a3[2*j+1] = fma2(xc, wv3.y, a3[2*j+1]);
                }
            }
#pragma unroll
            for (int dpp = 0; dpp < 4; dpp++) {
                F2U t0; t0.u = a1[2*dpp];
                F2U t1; t1.u = a1[2*dpp+1];
                sO1[(q * 4 + dpp) * NT4 + tid] =
                    make_uint2(h2u(__float22half2_rn(t0.f)), h2u(__float22half2_rn(t1.f)));
                F2U s0; s0.u = a3[2*dpp];
                F2U s1; s1.u = a3[2*dpp+1];
                sO3[(q * 4 + dpp) * NT4 + tid] =
                    make_uint2(h2u(__float22half2_rn(s0.f)), h2u(__float22half2_rn(s1.f)));
            }
        }

        // ---------- phase 2: o2[p], logits, softmax, apply ----------
        float* gco = g_cat + ((size_t)b * 288 + br * 144) * HW + hw;
#pragma unroll 1
        for (int p = 0; p < 9; p++) {
            const int yy = y + c_dy8[p] * s;
            const int xx = x + c_dx8[p] * s;
            const bool ok = ((unsigned)yy < (unsigned)Hd) && ((unsigned)xx < (unsigned)Wd);
            const float sgn = (p == 8) ? 1.f : -1.f;
            const float* hp = h + yy * Wd + xx;

            ull a2[8];
#pragma unroll
            for (int dp = 0; dp < 8; dp++) a2[dp] = 0ull;
#pragma unroll
            for (int c = 0; c < 16; c++) {
                float v = ok ? sgn * hp[c * HW] : 0.f;
                ull xc = pack2(v, v);
                const ulonglong2* wp = (const ulonglong2*)(s_w + 2304 + (((p * 16 + c) << 4)));
#pragma unroll
                for (int j = 0; j < 4; j++) {
                    ulonglong2 wv = wp[j];
                    a2[2*j]   = fma2(xc, wv.x, a2[2*j]);
                    a2[2*j+1] = fma2(xc, wv.y, a2[2*j+1]);
                }
            }
            float l[9];
#pragma unroll
            for (int q = 0; q < 9; q++) {
                ull acc = 0ull;
#pragma unroll
                for (int dpp = 0; dpp < 4; dpp++) {
                    uint2 u = sO1[(q * 4 + dpp) * NT4 + tid];
                    F2U fa; fa.f = __half22float2(u2h(u.x));
                    F2U fb; fb.f = __half22float2(u2h(u.y));
                    acc = fma2(a2[2*dpp],   fa.u, acc);
                    acc = fma2(a2[2*dpp+1], fb.u, acc);
                }
                F2U r; r.u = acc;
                l[q] = sc * (r.f.x + r.f.y);
            }
            float m = l[0];
#pragma unroll
            for (int q = 1; q < 9; q++) m = fmaxf(m, l[q]);
            float ss = 0.f;
#pragma unroll
            for (int q = 0; q < 9; q++) { l[q] = __expf(l[q] - m); ss += l[q]; }

            ull rp[8];
#pragma unroll
            for (int dp = 0; dp < 8; dp++) rp[dp] = 0ull;
#pragma unroll
            for (int q = 0; q < 9; q++) {
                ull e = pack2(l[q], l[q]);
#pragma unroll
                for (int dpp = 0; dpp < 4; dpp++) {
                    uint2 u = sO3[(q * 4 + dpp) * NT4 + tid];
                    F2U fa; fa.f = __half22float2(u2h(u.x));
                    F2U fb; fb.f = __half22float2(u2h(u.y));
                    rp[2*dpp]   = fma2(e, fa.u, rp[2*dpp]);
                    rp[2*dpp+1] = fma2(e, fb.u, rp[2*dpp+1]);
                }
            }
            const float inv = 1.f / ss;
#pragma unroll
            for (int dp = 0; dp < 8; dp++) {
                F2U t; t.u = rp[dp];
                gco[(size_t)((p << 4) + 2 * dp) * HW]     = t.f.x * inv;
                gco[(size_t)((p << 4) + 2 * dp + 1) * HW] = t.f.y * inv;
            }
        }
    }
}

// ================= K3: final 1x1 conv, K-chunk 32, dynamic smem ================
#define OUT_SMEM (2*32*128*4*2)   // sW + sX double buffered = 65536 B

__global__ void __launch_bounds__(256) out_kernel(
    const float* __restrict__ out_b, float* __restrict__ out)
{
    extern __shared__ float sm2[];
    // layout: sW[2][32][128] at 0 (8192 floats), sX[2][32][128] at 8192

    const int tid = threadIdx.x;
    const int to = tid >> 4;   // 0..15 -> 8 outputs
    const int tp = tid & 15;   // 0..15 -> 8 pixels
    const int b = blockIdx.y;
    const int px0 = blockIdx.x * 128;
    const float* catb = g_cat + (size_t)b * 288 * HW + px0;

    const unsigned swb = (unsigned)__cvta_generic_to_shared(sm2);
    const unsigned sxb = swb + 8192u * 4u;

    ull acc[8][4];
#pragma unroll
    for (int i = 0; i < 8; i++)
#pragma unroll
        for (int j = 0; j < 4; j++) acc[i][j] = 0ull;

    // prologue: stage chunk 0 into buf 0
    {
#pragma unroll
        for (int i = 0; i < 4; i++) {
            int idx = tid + i * 256;           // 0..1023
            int k = idx >> 5, c = (idx & 31) << 2;
            cp16(swb + (unsigned)((k * 128 + c) * 4), &g_wt[(0 * 32 + k) * 128 + c]);
            cp16(sxb + (unsigned)((k * 128 + c) * 4), &catb[(size_t)(0 * 32 + k) * HW + c]);
        }
        asm volatile("cp.async.commit_group;");
    }

#pragma unroll 1
    for (int kc = 0; kc < 9; kc++) {
        if (kc < 8) {
            const int nb = (kc + 1) & 1;
            const unsigned off = (unsigned)(nb * 32 * 128 * 4);
#pragma unroll
            for (int i = 0; i < 4; i++) {
                int idx = tid + i * 256;
                int k = idx >> 5, c = (idx & 31) << 2;
                cp16(swb + off + (unsigned)((k * 128 + c) * 4),
                     &g_wt[((kc + 1) * 32 + k) * 128 + c]);
                cp16(sxb + off + (unsigned)((k * 128 + c) * 4),
                     &catb[(size_t)((kc + 1) * 32 + k) * HW + c]);
            }
            asm volatile("cp.async.commit_group;");
            asm volatile("cp.async.wait_group 1;");
        } else {
            asm volatile("cp.async.wait_group 0;");
        }
        __syncthreads();

        const int buf = kc & 1;
        const float* wbase = sm2 + buf * 4096 + to * 8;
        const float* xbase = sm2 + 8192 + buf * 4096 + tp * 8;
#pragma unroll
        for (int k = 0; k < 32; k++) {
            const ulonglong2* xr = (const ulonglong2*)(xbase + k * 128);
            ulonglong2 xa = xr[0], xb = xr[1];
            const float4* wr = (const float4*)(wbase + k * 128);
            float4 wv0 = wr[0], wv1 = wr[1];
            float wsc[8] = {wv0.x, wv0.y, wv0.z, wv0.w, wv1.x, wv1.y, wv1.z, wv1.w};
#pragma unroll
            for (int i = 0; i < 8; i++) {
                ull wp = pack2(wsc[i], wsc[i]);
                acc[i][0] = fma2(wp, xa.x, acc[i][0]);
                acc[i][1] = fma2(wp, xa.y, acc[i][1]);
                acc[i][2] = fma2(wp, xb.x, acc[i][2]);
                acc[i][3] = fma2(wp, xb.y, acc[i][3]);
            }
        }
        __syncthreads();
    }

#pragma unroll
    for (int i = 0; i < 8; i++) {
        const int o = to * 8 + i;
        const float bias = out_b[o];
        float* op = out + ((size_t)b * 128 + o) * HW + px0 + tp * 8;
#pragma unroll
        for (int j = 0; j < 4; j++) {
            F2U a; a.u = acc[i][j];
            *(float2*)&op[2 * j] = make_float2(a.f.x + bias, a.f.y + bias);
        }
    }
}

// ================= launch =================
extern "C" void kernel_launch(void* const* d_in, const int* in_sizes, int n_in,
                              void* d_out, int out_size)
{
    const float* cen   = (const float*)d_in[0];
    const float* in_w0 = (const float*)d_in[1];
    const float* in_b0 = (const float*)d_in[2];
    const float* in_w1 = (const float*)d_in[3];
    const float* in_b1 = (const float*)d_in[4];
    const float* w1_0  = (const float*)d_in[5];
    const float* w2_0  = (const float*)d_in[6];
    const float* w3_0  = (const float*)d_in[7];
    const float* w1_1  = (const float*)d_in[8];
    const float* w2_1  = (const float*)d_in[9];
    const float* w3_1  = (const float*)d_in[10];
    const float* scale = (const float*)d_in[11];
    const float* out_w = (const float*)d_in[12];
    const float* out_b = (const float*)d_in[13];
    float* out = (float*)d_out;

    cudaFuncSetAttribute(attn_kernel, cudaFuncAttributeMaxDynamicSharedMemorySize, SMTOT4);
    cudaFuncSetAttribute(out_kernel, cudaFuncAttributeMaxDynamicSharedMemorySize, OUT_SMEM);

    wt_kernel<<<144, 256>>>(out_w);
    proj_kernel<<<dim3(12, 12, 4), dim3(16, 8)>>>(cen, in_w0, in_b0, in_w1, in_b1);
    attn_kernel<<<PIX / NT4, NT4, SMTOT4>>>(
        w1_0, w2_0, w3_0, w1_1, w2_1, w3_1, scale);
    out_kernel<<<dim3(HW / 128, BATCH), 256, OUT_SMEM>>>(out_b, out);
}

// round 15
// speedup vs baseline: 1.5342x; 1.5342x over previous
#include <cuda_runtime.h>
#include <cuda_fp16.h>

#define Wd 192
#define Hd 192
#define HW (192*192)
#define BATCH 4
#define PIX (BATCH*HW)
#define INC 256

// ---------------- scratch (no allocations allowed) ----------------
__device__ __align__(16) float g_h0[BATCH*16*HW];
__device__ __align__(16) float g_h1[BATCH*16*HW];
__device__ __align__(16) __half g_cat[(size_t)BATCH*288*HW];   // fp16 intermediate
__device__ __align__(16) float g_wt[288*128];

__constant__ int c_dy8[9] = {-1,-1,-1, 0, 1, 1, 1, 0, 0};
__constant__ int c_dx8[9] = {-1, 0, 1, 1, 1, 0,-1,-1, 0};

// ---------------- helpers ----------------
typedef unsigned long long ull;
union F2U { float2 f; ull u; };

__device__ __forceinline__ ull fma2(ull a, ull b, ull c) {
    ull d;
    asm("fma.rn.f32x2 %0, %1, %2, %3;" : "=l"(d) : "l"(a), "l"(b), "l"(c));
    return d;
}
__device__ __forceinline__ ull pack2(float x, float y) {
    F2U t; t.f = make_float2(x, y); return t.u;
}
__device__ __forceinline__ unsigned h2u(__half2 h) { return *(unsigned*)&h; }
__device__ __forceinline__ __half2 u2h(unsigned u) { return *(__half2*)&u; }

__device__ __forceinline__ void cp16(unsigned dst, const void* src) {
    asm volatile("cp.async.cg.shared.global [%0], [%1], 16;" :: "r"(dst), "l"(src));
}

// ================= K0: transpose out_w (128,288) -> (288,128) =================
__global__ void wt_kernel(const float* __restrict__ out_w) {
    int idx = blockIdx.x * 256 + threadIdx.x;
    if (idx < 128 * 288) {
        int o = idx / 288, i = idx % 288;
        g_wt[i * 128 + o] = out_w[idx];
    }
}

// ================= K1: fused 1x1 + 3x3 projection (2 px/thread) =================
__global__ void __launch_bounds__(128) proj_kernel(
    const float* __restrict__ cen,
    const float* __restrict__ w0, const float* __restrict__ b0,
    const float* __restrict__ w1, const float* __restrict__ b1)
{
    __shared__ __align__(16) float s_cen[16][18][18];
    __shared__ __align__(16) float s_w1[16][9][16];
    __shared__ __align__(16) float s_w0[16][16];

    const int tx = threadIdx.x;
    const int ty = threadIdx.y;
    const int tid = ty * 16 + tx;
    const int x0 = blockIdx.x * 16, y0 = blockIdx.y * 16;
    const int b  = blockIdx.z;

    ull acc0[2][8], acc1[2][8];
#pragma unroll
    for (int p = 0; p < 2; p++)
#pragma unroll
        for (int o = 0; o < 8; o++) { acc0[p][o] = 0ull; acc1[p][o] = 0ull; }

#pragma unroll 1
    for (int cc = 0; cc < 16; cc++) {
        for (int idx = tid; idx < 16 * 324; idx += 128) {
            int ci = idx / 324, rem = idx % 324;
            int ly = rem / 18, lx = rem % 18;
            int gy = y0 - 1 + ly, gx = x0 - 1 + lx;
            float v = 0.f;
            if ((unsigned)gy < (unsigned)Hd && (unsigned)gx < (unsigned)Wd)
                v = cen[(size_t)(b * INC + cc * 16 + ci) * HW + gy * Wd + gx];
            s_cen[ci][ly][lx] = v;
        }
        for (int idx = tid; idx < 2304; idx += 128) {
            int ci = idx / 144, rem = idx % 144;
            int t = rem / 16, o = rem % 16;
            s_w1[ci][t][o] = w1[(o * INC + cc * 16 + ci) * 9 + t];
        }
        for (int ii = tid; ii < 256; ii += 128) {
            int ci = ii / 16, o = ii % 16;
            s_w0[ci][o] = w0[o * INC + cc * 16 + ci];
        }
        __syncthreads();

#pragma unroll 1
        for (int ci = 0; ci < 16; ci++) {
#pragma unroll
            for (int px = 0; px < 2; px++) {
                const int ly = ty + px * 8;
                float v[9];
#pragma unroll
                for (int r = 0; r < 3; r++)
#pragma unroll
                    for (int c = 0; c < 3; c++)
                        v[r * 3 + c] = s_cen[ci][ly + r][tx + c];

                ull cv = pack2(v[4], v[4]);
                const ull* w0p = reinterpret_cast<const ull*>(&s_w0[ci][0]);
#pragma unroll
                for (int o2 = 0; o2 < 8; o2++)
                    acc0[px][o2] = fma2(cv, w0p[o2], acc0[px][o2]);
#pragma unroll
                for (int t = 0; t < 9; t++) {
                    ull tv = pack2(v[t], v[t]);
                    const ull* wp = reinterpret_cast<const ull*>(&s_w1[ci][t][0]);
#pragma unroll
                    for (int o2 = 0; o2 < 8; o2++)
                        acc1[px][o2] = fma2(tv, wp[o2], acc1[px][o2]);
                }
            }
        }
        __syncthreads();
    }

#pragma unroll
    for (int px = 0; px < 2; px++) {
        const int y = y0 + ty + px * 8, x = x0 + tx;
        const size_t base = (size_t)b * 16 * HW + (size_t)y * Wd + x;
#pragma unroll
        for (int o2 = 0; o2 < 8; o2++) {
            F2U a; a.u = acc0[px][o2];
            g_h0[base + (size_t)(2 * o2) * HW]     = a.f.x + b0[2 * o2];
            g_h0[base + (size_t)(2 * o2 + 1) * HW] = a.f.y + b0[2 * o2 + 1];
            F2U c; c.u = acc1[px][o2];
            g_h1[base + (size_t)(2 * o2) * HW]     = c.f.x + b1[2 * o2];
            g_h1[base + (size_t)(2 * o2 + 1) * HW] = c.f.y + b1[2 * o2 + 1];
        }
    }
}

// ================= K2: per-pixel attention, 2 px/thread, vectorized LDS =========
#define NT2 128
#define SO1_OFF 6912
#define SO3_OFF (6912 + 9*8*2*NT2)           // + 18432 words
#define SMTOT   ((6912 + 2*9*8*2*NT2) * 4)   // 175104 B

__global__ void __launch_bounds__(NT2) attn_kernel(
    const float* __restrict__ w1_0, const float* __restrict__ w2_0, const float* __restrict__ w3_0,
    const float* __restrict__ w1_1, const float* __restrict__ w2_1, const float* __restrict__ w3_1,
    const float* __restrict__ scale)
{
    extern __shared__ float sm[];
    float* s_w = sm;                              // w1t | w2t | w3t [(g*16+c)*16+d]
    uint2* sO1 = (uint2*)(sm + SO1_OFF);
    uint2* sO3 = (uint2*)(sm + SO3_OFF);

    const int tid = threadIdx.x;
    const int pid0 = blockIdx.x * (2 * NT2) + 2 * tid;
    const int b  = pid0 / HW;
    const int hw0 = pid0 % HW;
    const int y = hw0 / Wd, x0 = hw0 % Wd;

#pragma unroll 1
    for (int br = 0; br < 2; br++) {
        const float* h  = (br ? g_h1 : g_h0) + (size_t)b * 16 * HW;
        const float* w1 = br ? w1_1 : w1_0;
        const float* w2 = br ? w2_1 : w2_0;
        const float* w3 = br ? w3_1 : w3_0;
        const int   s  = br ? 5 : 1;
        const float sc = scale[br];

        __syncthreads();
        for (int i = tid; i < 2304; i += NT2) {
            int g = i >> 8; int rem = i & 255;
            int d = rem >> 4, c = rem & 15;
            int tix = ((g * 16 + c) << 4) + d;
            s_w[tix]        = w1[i];
            s_w[2304 + tix] = w2[i];
            s_w[4608 + tix] = w3[i];
        }
        __syncthreads();

        // ---------- phase 1: o1[q], o3[q] -> fp16 smem ----------
#pragma unroll 1
        for (int q = 0; q < 9; q++) {
            const int yy = y + c_dy8[q] * s;
            const int xxa = x0 + c_dx8[q] * s;
            const bool oky = (unsigned)yy < (unsigned)Hd;
            const bool ok0 = oky && (unsigned)xxa < (unsigned)Wd;
            const bool ok1 = oky && (unsigned)(xxa + 1) < (unsigned)Wd;
            const float sgn = (q == 8) ? 1.f : -1.f;
            const float* hrow = h + yy * Wd;

            float xv0[16], xv1[16];
#pragma unroll
            for (int c = 0; c < 16; c++) {
                float v0 = ok0 ? hrow[c * HW + xxa] : 0.f;
                float v1 = ok1 ? hrow[c * HW + xxa + 1] : 0.f;
                xv0[c] = sgn * v0; xv1[c] = sgn * v1;
            }
            ull a1[2][8], a3[2][8];
#pragma unroll
            for (int dp = 0; dp < 8; dp++) {
                a1[0][dp] = 0ull; a1[1][dp] = 0ull;
                a3[0][dp] = 0ull; a3[1][dp] = 0ull;
            }
#pragma unroll
            for (int c = 0; c < 16; c++) {
                ull xc0 = pack2(xv0[c], xv0[c]);
                ull xc1 = pack2(xv1[c], xv1[c]);
                const ulonglong2* wp1 = (const ulonglong2*)(s_w + (((q * 16 + c) << 4)));
                const ulonglong2* wp3 = (const ulonglong2*)(s_w + 4608 + (((q * 16 + c) << 4)));
#pragma unroll
                for (int j = 0; j < 4; j++) {
                    ulonglong2 wv1 = wp1[j];
                    a1[0][2*j]   = fma2(xc0, wv1.x, a1[0][2*j]);
                    a1[0][2*j+1] = fma2(xc0, wv1.y, a1[0][2*j+1]);
                    a1[1][2*j]   = fma2(xc1, wv1.x, a1[1][2*j]);
                    a1[1][2*j+1] = fma2(xc1, wv1.y, a1[1][2*j+1]);
                    ulonglong2 wv3 = wp3[j];
                    a3[0][2*j]   = fma2(xc0, wv3.x, a3[0][2*j]);
                    a3[0][2*j+1] = fma2(xc0, wv3.y, a3[0][2*j+1]);
                    a3[1][2*j]   = fma2(xc1, wv3.x, a3[1][2*j]);
                    a3[1][2*j+1] = fma2(xc1, wv3.y, a3[1][2*j+1]);
                }
            }
#pragma unroll
            for (int pxi = 0; pxi < 2; pxi++)
#pragma unroll
                for (int dpp = 0; dpp < 4; dpp++) {
                    F2U t0; t0.u = a1[pxi][2*dpp];
                    F2U t1; t1.u = a1[pxi][2*dpp+1];
                    uint2 v1v = make_uint2(h2u(__float22half2_rn(t0.f)),
                                           h2u(__float22half2_rn(t1.f)));
                    sO1[(((q * 4 + dpp) << 1) + pxi) * NT2 + tid] = v1v;
                    F2U s0; s0.u = a3[pxi][2*dpp];
                    F2U s1; s1.u = a3[pxi][2*dpp+1];
                    uint2 v3v = make_uint2(h2u(__float22half2_rn(s0.f)),
                                           h2u(__float22half2_rn(s1.f)));
                    sO3[(((q * 4 + dpp) << 1) + pxi) * NT2 + tid] = v3v;
                }
        }

        // ---------- phase 2+3: o2[p], logits, softmax, apply ----------
        __half* gco = g_cat + ((size_t)b * 288 + br * 144) * HW + hw0;
#pragma unroll 1
        for (int p = 0; p < 9; p++) {
            const int yy = y + c_dy8[p] * s;
            const int xxa = x0 + c_dx8[p] * s;
            const bool oky = (unsigned)yy < (unsigned)Hd;
            const bool ok0 = oky && (unsigned)xxa < (unsigned)Wd;
            const bool ok1 = oky && (unsigned)(xxa + 1) < (unsigned)Wd;
            const float sgn = (p == 8) ? 1.f : -1.f;
            const float* hrow = h + yy * Wd;

            ull a2[2][8];
#pragma unroll
            for (int dp = 0; dp < 8; dp++) { a2[0][dp] = 0ull; a2[1][dp] = 0ull; }
#pragma unroll
            for (int c = 0; c < 16; c++) {
                float v0 = ok0 ? hrow[c * HW + xxa] : 0.f;
                float v1 = ok1 ? hrow[c * HW + xxa + 1] : 0.f;
                ull xc0 = pack2(sgn * v0, sgn * v0);
                ull xc1 = pack2(sgn * v1, sgn * v1);
                const ulonglong2* wp = (const ulonglong2*)(s_w + 2304 + (((p * 16 + c) << 4)));
#pragma unroll
                for (int j = 0; j < 4; j++) {
                    ulonglong2 wv = wp[j];
                    a2[0][2*j]   = fma2(xc0, wv.x, a2[0][2*j]);
                    a2[0][2*j+1] = fma2(xc0, wv.y, a2[0][2*j+1]);
                    a2[1][2*j]   = fma2(xc1, wv.x, a2[1][2*j]);
                    a2[1][2*j+1] = fma2(xc1, wv.y, a2[1][2*j+1]);
                }
            }
            float l0[9], l1[9];
#pragma unroll
            for (int q = 0; q < 9; q++) {
                ull acc0 = 0ull, acc1 = 0ull;
#pragma unroll
                for (int dpp = 0; dpp < 4; dpp++) {
                    uint2 u0 = sO1[(((q * 4 + dpp) << 1) + 0) * NT2 + tid];
                    uint2 u1 = sO1[(((q * 4 + dpp) << 1) + 1) * NT2 + tid];
                    F2U f0a; f0a.f = __half22float2(u2h(u0.x));
                    F2U f0b; f0b.f = __half22float2(u2h(u0.y));
                    F2U f1a; f1a.f = __half22float2(u2h(u1.x));
                    F2U f1b; f1b.f = __half22float2(u2h(u1.y));
                    acc0 = fma2(a2[0][2*dpp],   f0a.u, acc0);
                    acc0 = fma2(a2[0][2*dpp+1], f0b.u, acc0);
                    acc1 = fma2(a2[1][2*dpp],   f1a.u, acc1);
                    acc1 = fma2(a2[1][2*dpp+1], f1b.u, acc1);
                }
                F2U r0; r0.u = acc0; l0[q] = sc * (r0.f.x + r0.f.y);
                F2U r1; r1.u = acc1; l1[q] = sc * (r1.f.x + r1.f.y);
            }
            float m0 = l0[0], m1 = l1[0];
#pragma unroll
            for (int q = 1; q < 9; q++) { m0 = fmaxf(m0, l0[q]); m1 = fmaxf(m1, l1[q]); }
            float ss0 = 0.f, ss1 = 0.f;
#pragma unroll
            for (int q = 0; q < 9; q++) {
                l0[q] = __expf(l0[q] - m0); ss0 += l0[q];
                l1[q] = __expf(l1[q] - m1); ss1 += l1[q];
            }
            ull rp0[8], rp1[8];
#pragma unroll
            for (int dp = 0; dp < 8; dp++) { rp0[dp] = 0ull; rp1[dp] = 0ull; }
#pragma unroll
            for (int q = 0; q < 9; q++) {
                ull e0 = pack2(l0[q], l0[q]);
                ull e1 = pack2(l1[q], l1[q]);
#pragma unroll
                for (int dpp = 0; dpp < 4; dpp++) {
                    uint2 u0 = sO3[(((q * 4 + dpp) << 1) + 0) * NT2 + tid];
                    uint2 u1 = sO3[(((q * 4 + dpp) << 1) + 1) * NT2 + tid];
                    F2U f0a; f0a.f = __half22float2(u2h(u0.x));
                    F2U f0b; f0b.f = __half22float2(u2h(u0.y));
                    F2U f1a; f1a.f = __half22float2(u2h(u1.x));
                    F2U f1b; f1b.f = __half22float2(u2h(u1.y));
                    rp0[2*dpp]   = fma2(e0, f0a.u, rp0[2*dpp]);
                    rp0[2*dpp+1] = fma2(e0, f0b.u, rp0[2*dpp+1]);
                    rp1[2*dpp]   = fma2(e1, f1a.u, rp1[2*dpp]);
                    rp1[2*dpp+1] = fma2(e1, f1b.u, rp1[2*dpp+1]);
                }
            }
            const float inv0 = 1.f / ss0, inv1 = 1.f / ss1;
            // fp16 stores: each channel -> half2 over the 2 pixels
#pragma unroll
            for (int dp = 0; dp < 8; dp++) {
                F2U t0; t0.u = rp0[dp];   // (ch 2dp, ch 2dp+1) at px0
                F2U t1; t1.u = rp1[dp];   // same at px1
                __half2 hlo = __floats2half2_rn(t0.f.x * inv0, t1.f.x * inv1);
                __half2 hhi = __floats2half2_rn(t0.f.y * inv0, t1.f.y * inv1);
                *(__half2*)&gco[(size_t)((p << 4) + 2 * dp) * HW]     = hlo;
                *(__half2*)&gco[(size_t)((p << 4) + 2 * dp + 1) * HW] = hhi;
            }
        }
    }
}

// ================= K3: final 1x1 conv, fp16 X tile =============================
__global__ void __launch_bounds__(256) out_kernel(
    const float* __restrict__ out_b, float* __restrict__ out)
{
    __shared__ __align__(16) float  sW[2][16][128];
    __shared__ __align__(16) __half sX[2][16][128];

    const int tid = threadIdx.x;
    const int to = tid >> 4;   // 0..15 -> 8 outputs
    const int tp = tid & 15;   // 0..15 -> 8 pixels
    const int b = blockIdx.y;
    const int px0 = blockIdx.x * 128;
    const __half* catb = g_cat + (size_t)b * 288 * HW + px0;

    const unsigned swb = (unsigned)__cvta_generic_to_shared(&sW[0][0][0]);
    const unsigned sxb = (unsigned)__cvta_generic_to_shared(&sX[0][0][0]);

    ull acc[8][4];
#pragma unroll
    for (int i = 0; i < 8; i++)
#pragma unroll
        for (int j = 0; j < 4; j++) acc[i][j] = 0ull;

    // prologue: stage chunk 0 into buf 0
    {
        // W: 16 rows x 128 floats = 512 x 16B -> 2 rounds
#pragma unroll
        for (int i = 0; i < 2; i++) {
            int idx = tid + i * 256;
            int k = idx >> 5, c = (idx & 31) << 2;
            cp16(swb + (unsigned)((k * 128 + c) * 4), &g_wt[(0 * 16 + k) * 128 + c]);
        }
        // X: 16 rows x 128 halves = 256 x 16B -> 1 round
        {
            int k = tid >> 4, c8 = (tid & 15) << 3;
            cp16(sxb + (unsigned)((k * 128 + c8) * 2), &catb[(size_t)(0 * 16 + k) * HW + c8]);
        }
        asm volatile("cp.async.commit_group;");
    }

#pragma unroll 1
    for (int kc = 0; kc < 18; kc++) {
        if (kc < 17) {
            const int nb = (kc + 1) & 1;
            const unsigned offW = (unsigned)(nb * 16 * 128 * 4);
            const unsigned offX = (unsigned)(nb * 16 * 128 * 2);
#pragma unroll
            for (int i = 0; i < 2; i++) {
                int idx = tid + i * 256;
                int k = idx >> 5, c = (idx & 31) << 2;
                cp16(swb + offW + (unsigned)((k * 128 + c) * 4),
                     &g_wt[((kc + 1) * 16 + k) * 128 + c]);
            }
            {
                int k = tid >> 4, c8 = (tid & 15) << 3;
                cp16(sxb + offX + (unsigned)((k * 128 + c8) * 2),
                     &catb[(size_t)((kc + 1) * 16 + k) * HW + c8]);
            }
            asm volatile("cp.async.commit_group;");
            asm volatile("cp.async.wait_group 1;");
        } else {
            asm volatile("cp.async.wait_group 0;");
        }
        __syncthreads();

        const int buf = kc & 1;
#pragma unroll
        for (int k = 0; k < 16; k++) {
            // X: 1 x LDS.128 -> 8 halves (8 px), convert to 4 f32x2 pairs
            uint4 xh = *(const uint4*)&sX[buf][k][tp * 8];
            F2U xa, xbv, xc, xd;
            xa.f  = __half22float2(u2h(xh.x));
            xbv.f = __half22float2(u2h(xh.y));
            xc.f  = __half22float2(u2h(xh.z));
            xd.f  = __half22float2(u2h(xh.w));
            const float* wr = &sW[buf][k][to * 8];
#pragma unroll
            for (int i = 0; i < 8; i++) {
                ull wp = pack2(wr[i], wr[i]);
                acc[i][0] = fma2(wp, xa.u,  acc[i][0]);
                acc[i][1] = fma2(wp, xbv.u, acc[i][1]);
                acc[i][2] = fma2(wp, xc.u,  acc[i][2]);
                acc[i][3] = fma2(wp, xd.u,  acc[i][3]);
            }
        }
        __syncthreads();
    }

#pragma unroll
    for (int i = 0; i < 8; i++) {
        const int o = to * 8 + i;
        const float bias = out_b[o];
        float* op = out + ((size_t)b * 128 + o) * HW + px0 + tp * 8;
#pragma unroll
        for (int j = 0; j < 4; j++) {
            F2U a; a.u = acc[i][j];
            *(float2*)&op[2 * j] = make_float2(a.f.x + bias, a.f.y + bias);
        }
    }
}

// ================= launch =================
extern "C" void kernel_launch(void* const* d_in, const int* in_sizes, int n_in,
                              void* d_out, int out_size)
{
    const float* cen   = (const float*)d_in[0];
    const float* in_w0 = (const float*)d_in[1];
    const float* in_b0 = (const float*)d_in[2];
    const float* in_w1 = (const float*)d_in[3];
    const float* in_b1 = (const float*)d_in[4];
    const float* w1_0  = (const float*)d_in[5];
    const float* w2_0  = (const float*)d_in[6];
    const float* w3_0  = (const float*)d_in[7];
    const float* w1_1  = (const float*)d_in[8];
    const float* w2_1  = (const float*)d_in[9];
    const float* w3_1  = (const float*)d_in[10];
    const float* scale = (const float*)d_in[11];
    const float* out_w = (const float*)d_in[12];
    const float* out_b = (const float*)d_in[13];
    float* out = (float*)d_out;

    cudaFuncSetAttribute(attn_kernel, cudaFuncAttributeMaxDynamicSharedMemorySize, SMTOT);

    wt_kernel<<<144, 256>>>(out_w);
    proj_kernel<<<dim3(12, 12, 4), dim3(16, 8)>>>(cen, in_w0, in_b0, in_w1, in_b1);
    attn_kernel<<<PIX / (2 * NT2), NT2, SMTOT>>>(
        w1_0, w2_0, w3_0, w1_1, w2_1, w3_1, scale);
    out_kernel<<<dim3(HW / 128, BATCH), 256>>>(out_b, out);
}